// round 2
// baseline (speedup 1.0000x reference)
#include <cuda_runtime.h>
#include <stdint.h>

#define MAX_NODES 75008
#define MAX_EDGES 1200000
#define F 64

// scratch (device globals; no runtime allocation allowed)
__device__ float g_agg[(size_t)MAX_NODES * F];
__device__ int   g_cnt[MAX_NODES];
__device__ int   g_off[MAX_NODES + 1];
__device__ int   g_cur[MAX_NODES];
__device__ int   g_ssrc[MAX_EDGES];   // src ids sorted by dst

__global__ void zero_cnt_kernel(int N) {
    int i = blockIdx.x * blockDim.x + threadIdx.x;
    if (i < N) g_cnt[i] = 0;
}

__global__ void hist_kernel(const int* __restrict__ dst, int E) {
    int e = blockIdx.x * blockDim.x + threadIdx.x;
    if (e < E) atomicAdd(&g_cnt[dst[e]], 1);
}

// single-block exclusive scan over g_cnt -> g_off, g_cur; g_off[N] = E
__global__ void scan_kernel(int N, int E) {
    __shared__ int part[1024];
    int t = threadIdx.x;
    int chunk = (N + 1023) >> 10;
    int lo = t * chunk;
    int hi = min(lo + chunk, N);
    int sum = 0;
    for (int i = lo; i < hi; i++) sum += g_cnt[i];
    part[t] = sum;
    __syncthreads();
    #pragma unroll
    for (int d = 1; d < 1024; d <<= 1) {
        int v = (t >= d) ? part[t - d] : 0;
        __syncthreads();
        part[t] += v;
        __syncthreads();
    }
    int run = part[t] - sum;  // exclusive prefix
    for (int i = lo; i < hi; i++) {
        g_off[i] = run;
        g_cur[i] = run;
        run += g_cnt[i];
    }
    if (t == 0) g_off[N] = E;
}

__global__ void place_kernel(const int* __restrict__ src,
                             const int* __restrict__ dst, int E) {
    int e = blockIdx.x * blockDim.x + threadIdx.x;
    if (e < E) {
        int d = dst[e];
        int pos = atomicAdd(&g_cur[d], 1);
        g_ssrc[pos] = src[e];
    }
}

// pull-gather: one warp per dst node. lane owns 2 feature columns (float2).
// agg[node] = (1/sqrt(deg[node])) * sum_{e in CSR row} feat[src_e] / sqrt(deg[src_e])
__global__ void gather_kernel(const float* __restrict__ feat,
                              const float* __restrict__ deg,
                              int N) {
    int w = (int)(((size_t)blockIdx.x * blockDim.x + threadIdx.x) >> 5);
    int lane = threadIdx.x & 31;
    if (w >= N) return;

    int start = g_off[w];
    int end   = g_off[w + 1];
    const float2* f2 = reinterpret_cast<const float2*>(feat);

    float ax = 0.f, ay = 0.f;
    int j = start;
    for (; j + 4 <= end; j += 4) {
        int s0 = g_ssrc[j], s1 = g_ssrc[j + 1], s2 = g_ssrc[j + 2], s3 = g_ssrc[j + 3];
        float i0 = rsqrtf(__ldg(deg + s0));
        float i1 = rsqrtf(__ldg(deg + s1));
        float i2 = rsqrtf(__ldg(deg + s2));
        float i3 = rsqrtf(__ldg(deg + s3));
        float2 v0 = __ldg(f2 + (size_t)s0 * 32 + lane);
        float2 v1 = __ldg(f2 + (size_t)s1 * 32 + lane);
        float2 v2 = __ldg(f2 + (size_t)s2 * 32 + lane);
        float2 v3 = __ldg(f2 + (size_t)s3 * 32 + lane);
        ax += v0.x * i0 + v1.x * i1 + v2.x * i2 + v3.x * i3;
        ay += v0.y * i0 + v1.y * i1 + v2.y * i2 + v3.y * i3;
    }
    for (; j < end; j++) {
        int s = g_ssrc[j];
        float is = rsqrtf(__ldg(deg + s));
        float2 v = __ldg(f2 + (size_t)s * 32 + lane);
        ax += v.x * is;
        ay += v.y * is;
    }

    float isd = rsqrtf(__ldg(deg + w));
    float2 r = make_float2(ax * isd, ay * isd);
    reinterpret_cast<float2*>(g_agg)[(size_t)w * 32 + lane] = r;
}

// out[64-row tile] = agg_tile @ W + b  (agg already fully degree-scaled)
__global__ void apply_kernel(const float* __restrict__ W,
                             const float* __restrict__ b,
                             float* __restrict__ out,
                             int N) {
    __shared__ float As[64][68];   // As[k][row]
    __shared__ float Ws[64 * 64];  // Ws[k*64 + col]
    __shared__ float bs[64];

    int tid  = threadIdx.x;
    int base = blockIdx.x * 64;

    #pragma unroll
    for (int i = tid; i < 4096; i += 256) Ws[i] = W[i];
    if (tid < 64) bs[tid] = b[tid];

    #pragma unroll
    for (int i = tid; i < 4096; i += 256) {
        int r = i >> 6, c = i & 63;
        int node = base + r;
        float v = 0.f;
        if (node < N) v = g_agg[(size_t)node * F + c];
        As[c][r] = v;
    }
    __syncthreads();

    int tx = tid & 15, ty = tid >> 4;
    float acc[4][4];
    #pragma unroll
    for (int i = 0; i < 4; i++)
        #pragma unroll
        for (int jj = 0; jj < 4; jj++) acc[i][jj] = 0.f;

    #pragma unroll
    for (int k = 0; k < 64; k++) {
        float4 a = *reinterpret_cast<const float4*>(&As[k][ty * 4]);
        float4 w = *reinterpret_cast<const float4*>(&Ws[k * 64 + tx * 4]);
        acc[0][0] += a.x * w.x; acc[0][1] += a.x * w.y; acc[0][2] += a.x * w.z; acc[0][3] += a.x * w.w;
        acc[1][0] += a.y * w.x; acc[1][1] += a.y * w.y; acc[1][2] += a.y * w.z; acc[1][3] += a.y * w.w;
        acc[2][0] += a.z * w.x; acc[2][1] += a.z * w.y; acc[2][2] += a.z * w.z; acc[2][3] += a.z * w.w;
        acc[3][0] += a.w * w.x; acc[3][1] += a.w * w.y; acc[3][2] += a.w * w.z; acc[3][3] += a.w * w.w;
    }

    float4 bb = *reinterpret_cast<const float4*>(&bs[tx * 4]);
    #pragma unroll
    for (int i = 0; i < 4; i++) {
        int node = base + ty * 4 + i;
        if (node < N) {
            float4 r4 = make_float4(acc[i][0] + bb.x, acc[i][1] + bb.y,
                                    acc[i][2] + bb.z, acc[i][3] + bb.w);
            *reinterpret_cast<float4*>(out + (size_t)node * F + tx * 4) = r4;
        }
    }
}

extern "C" void kernel_launch(void* const* d_in, const int* in_sizes, int n_in,
                              void* d_out, int out_size) {
    const float* feature = (const float*)d_in[0];
    const float* degree  = (const float*)d_in[1];
    const int*   src     = (const int*)d_in[2];
    const int*   dst     = (const int*)d_in[3];
    const float* W       = (const float*)d_in[4];
    const float* b       = (const float*)d_in[5];
    float* out = (float*)d_out;

    int N = in_sizes[1];        // 75000 nodes
    int E = in_sizes[2];        // 1200000 edges

    zero_cnt_kernel<<<(N + 255) / 256, 256>>>(N);
    hist_kernel<<<(E + 255) / 256, 256>>>(dst, E);
    scan_kernel<<<1, 1024>>>(N, E);
    place_kernel<<<(E + 255) / 256, 256>>>(src, dst, E);
    gather_kernel<<<(N + 7) / 8, 256>>>(feature, degree, N);   // 8 warps/block
    apply_kernel<<<(N + 63) / 64, 256>>>(W, b, out, N);
}

// round 3
// speedup vs baseline: 2.2211x; 2.2211x over previous
#include <cuda_runtime.h>
#include <stdint.h>

#define MAX_NODES 75008
#define F 64

// scratch: aggregated messages per node, zeroed each launch
__device__ __align__(256) float g_agg[(size_t)MAX_NODES * F];

__global__ void zero_agg_kernel(int n4) {
    int i = blockIdx.x * blockDim.x + threadIdx.x;
    if (i < n4) reinterpret_cast<float4*>(g_agg)[i] = make_float4(0.f, 0.f, 0.f, 0.f);
}

__device__ __forceinline__ void red_add_v4(float* addr, float x, float y, float z, float w) {
    asm volatile("red.global.add.v4.f32 [%0], {%1, %2, %3, %4};"
                 :: "l"(addr), "f"(x), "f"(y), "f"(z), "f"(w)
                 : "memory");
}

// 16 lanes per edge; each lane owns one float4 of the 64-float feature row.
// Gather feat[src]*rsqrt(deg[src]), vector-reduce into agg[dst].
__global__ void scatter_kernel(const float* __restrict__ feat,
                               const float* __restrict__ deg,
                               const int*   __restrict__ src,
                               const int*   __restrict__ dst,
                               int E) {
    size_t t = (size_t)blockIdx.x * blockDim.x + threadIdx.x;
    int e    = (int)(t >> 4);
    int lane = (int)(t & 15);
    if (e >= E) return;

    int s = __ldg(src + e);
    int d = __ldg(dst + e);
    float isd = rsqrtf(__ldg(deg + s));
    float4 v = __ldg(reinterpret_cast<const float4*>(feat) + (size_t)s * 16 + lane);

    float* o = g_agg + (size_t)d * F + lane * 4;
    red_add_v4(o, v.x * isd, v.y * isd, v.z * isd, v.w * isd);
}

// out[64-row tile] = (agg * rsqrt(deg)) @ W + b
__global__ void apply_kernel(const float* __restrict__ deg,
                             const float* __restrict__ W,
                             const float* __restrict__ b,
                             float* __restrict__ out,
                             int N) {
    __shared__ float As[64][68];   // As[k][row]
    __shared__ float Ws[64 * 64];  // Ws[k*64 + col]
    __shared__ float bs[64];

    int tid  = threadIdx.x;
    int base = blockIdx.x * 64;

    #pragma unroll
    for (int i = tid; i < 4096; i += 256) Ws[i] = W[i];
    if (tid < 64) bs[tid] = b[tid];

    #pragma unroll
    for (int i = tid; i < 4096; i += 256) {
        int r = i >> 6, c = i & 63;
        int node = base + r;
        float v = 0.f;
        if (node < N) v = g_agg[(size_t)node * F + c] * rsqrtf(__ldg(deg + node));
        As[c][r] = v;
    }
    __syncthreads();

    int tx = tid & 15, ty = tid >> 4;
    float acc[4][4];
    #pragma unroll
    for (int i = 0; i < 4; i++)
        #pragma unroll
        for (int j = 0; j < 4; j++) acc[i][j] = 0.f;

    #pragma unroll
    for (int k = 0; k < 64; k++) {
        float4 a = *reinterpret_cast<const float4*>(&As[k][ty * 4]);
        float4 w = *reinterpret_cast<const float4*>(&Ws[k * 64 + tx * 4]);
        acc[0][0] += a.x * w.x; acc[0][1] += a.x * w.y; acc[0][2] += a.x * w.z; acc[0][3] += a.x * w.w;
        acc[1][0] += a.y * w.x; acc[1][1] += a.y * w.y; acc[1][2] += a.y * w.z; acc[1][3] += a.y * w.w;
        acc[2][0] += a.z * w.x; acc[2][1] += a.z * w.y; acc[2][2] += a.z * w.z; acc[2][3] += a.z * w.w;
        acc[3][0] += a.w * w.x; acc[3][1] += a.w * w.y; acc[3][2] += a.w * w.z; acc[3][3] += a.w * w.w;
    }

    float4 bb = *reinterpret_cast<const float4*>(&bs[tx * 4]);
    #pragma unroll
    for (int i = 0; i < 4; i++) {
        int node = base + ty * 4 + i;
        if (node < N) {
            float4 r4 = make_float4(acc[i][0] + bb.x, acc[i][1] + bb.y,
                                    acc[i][2] + bb.z, acc[i][3] + bb.w);
            *reinterpret_cast<float4*>(out + (size_t)node * F + tx * 4) = r4;
        }
    }
}

extern "C" void kernel_launch(void* const* d_in, const int* in_sizes, int n_in,
                              void* d_out, int out_size) {
    const float* feature = (const float*)d_in[0];
    const float* degree  = (const float*)d_in[1];
    const int*   src     = (const int*)d_in[2];
    const int*   dst     = (const int*)d_in[3];
    const float* W       = (const float*)d_in[4];
    const float* b       = (const float*)d_in[5];
    float* out = (float*)d_out;

    int N = in_sizes[1];        // 75000 nodes
    int E = in_sizes[2];        // 1200000 edges

    int n4 = (N * F) / 4;
    zero_agg_kernel<<<(n4 + 255) / 256, 256>>>(n4);

    // 16 lanes per edge, 256 threads/block -> 16 edges per block
    scatter_kernel<<<(E + 15) / 16, 256>>>(feature, degree, src, dst, E);

    apply_kernel<<<(N + 63) / 64, 256>>>(degree, W, b, out, N);
}